// round 15
// baseline (speedup 1.0000x reference)
#include <cuda_runtime.h>
#include <cuda_bf16.h>
#include <cstdint>

// Problem constants
#define CCH  1024      // 4*FOUT
#define RR   4096      // B*N
#define FF   256

// Scratch (device globals; no allocation allowed)
__device__ float g_hpre[RR * CCH];   // concat [self, h1, h2, h3] pre-norm
__device__ float g_yn[RR * FF];      // x @ Wn^T (no bias)
__device__ float g_sqn[RR];          // per-row sum of squares (atomics)
__device__ float g_sum[CCH];
__device__ float g_sumsq[CCH];

// pre-split bf16 planes (X: [4096][256], W combined [Wx;Wn]: [512][256])
__device__ uint2 g_xhi[RR * FF / 4];
__device__ uint2 g_xlo[RR * FF / 4];
__device__ uint2 g_whi[512 * FF / 4];
__device__ uint2 g_wlo[512 * FF / 4];

// ---------------------------------------------------------------------------
// MMA helpers (bf16 m16n8k16, fp32 accum)
// ---------------------------------------------------------------------------
__device__ __forceinline__ void mma16816(float c[4], uint32_t a0, uint32_t a1,
                                         uint32_t a2, uint32_t a3,
                                         uint32_t b0, uint32_t b1) {
    asm volatile(
        "mma.sync.aligned.m16n8k16.row.col.f32.bf16.bf16.f32 "
        "{%0,%1,%2,%3}, {%4,%5,%6,%7}, {%8,%9}, {%0,%1,%2,%3};"
        : "+f"(c[0]), "+f"(c[1]), "+f"(c[2]), "+f"(c[3])
        : "r"(a0), "r"(a1), "r"(a2), "r"(a3), "r"(b0), "r"(b1));
}

__device__ __forceinline__ void ldsm4(uint32_t r[4], uint32_t addr) {
    asm volatile("ldmatrix.sync.aligned.m8n8.x4.shared.b16 {%0,%1,%2,%3}, [%4];"
                 : "=r"(r[0]), "=r"(r[1]), "=r"(r[2]), "=r"(r[3]) : "r"(addr));
}

__device__ __forceinline__ void cp16(uint32_t saddr, const void* gaddr) {
    asm volatile("cp.async.cg.shared.global [%0], [%1], 16;"
                 :: "r"(saddr), "l"(gaddr));
}

__device__ __forceinline__ uint32_t pack_bf16(float a, float b) {
    __nv_bfloat162 t = __halves2bfloat162(__float2bfloat16_rn(a),
                                          __float2bfloat16_rn(b));
    return *reinterpret_cast<uint32_t*>(&t);
}

// split fp32 float4 -> hi pair-packed (2 regs) and lo pair-packed (2 regs)
__device__ __forceinline__ void split4(float4 v, uint2& hi, uint2& lo) {
    float hx = __bfloat162float(__float2bfloat16_rn(v.x));
    float hy = __bfloat162float(__float2bfloat16_rn(v.y));
    float hz = __bfloat162float(__float2bfloat16_rn(v.z));
    float hw = __bfloat162float(__float2bfloat16_rn(v.w));
    hi.x = pack_bf16(v.x, v.y);
    hi.y = pack_bf16(v.z, v.w);
    lo.x = pack_bf16(v.x - hx, v.y - hy);
    lo.y = pack_bf16(v.z - hz, v.w - hw);
}

// ---------------------------------------------------------------------------
// K0: pre-split X and W=[Wx;Wn] into bf16 hi/lo planes; zero accumulators.
// ---------------------------------------------------------------------------
__global__ __launch_bounds__(256) void k_split(const float* __restrict__ X,
                                               const float* __restrict__ Wx,
                                               const float* __restrict__ Wn) {
    int i = blockIdx.x * 256 + threadIdx.x;
    if (i < 262144) {
        float4 v = ((const float4*)X)[i];
        uint2 hi, lo; split4(v, hi, lo);
        g_xhi[i] = hi; g_xlo[i] = lo;
    } else {
        int j = i - 262144;                 // 0..32767
        float4 v = (j < 16384) ? ((const float4*)Wx)[j]
                               : ((const float4*)Wn)[j - 16384];
        uint2 hi, lo; split4(v, hi, lo);
        g_whi[j] = hi; g_wlo[j] = lo;
        if (j < 4096) g_sqn[j] = 0.f;
        if (j < 256) {                       // fold k_zero
            ((float*)g_sum)[j]     = 0.f; ((float*)g_sum)[j + 256]   = 0.f;
            ((float*)g_sum)[j+512] = 0.f; ((float*)g_sum)[j + 768]   = 0.f;
            ((float*)g_sumsq)[j]     = 0.f; ((float*)g_sumsq)[j + 256] = 0.f;
            ((float*)g_sumsq)[j+512] = 0.f; ((float*)g_sumsq)[j + 768] = 0.f;
        }
    }
}

// ---------------------------------------------------------------------------
// K1: C[4096,512] = X[4096,256] @ W^T via split-bf16 tensor-core MMA.
// CTA tile 128(M) x 64(N), grid (8,32)=256 blocks, cp.async double buffer.
// Self blocks additionally accumulate per-row sum-of-squares into g_sqn.
// (byte-identical to the 49.3us best)
// ---------------------------------------------------------------------------
__global__ __launch_bounds__(256) void k_gemm(const float* __restrict__ bx) {
    extern __shared__ uint8_t sm[];
    const uint32_t AHI = 0, ALO = 16384, BHI = 32768, BLO = 40960;
    const uint32_t BUFSZ = 49152;
    const uint32_t sbase = (uint32_t)__cvta_generic_to_shared(sm);

    const int t  = threadIdx.x;
    const int m0 = blockIdx.y * 128;
    const int c0 = blockIdx.x * 64;          // combined W row base (0..448)
    const bool self = (c0 < 256);

    const uint4* Xhi = (const uint4*)g_xhi;  // row stride 32 uint4
    const uint4* Xlo = (const uint4*)g_xlo;
    const uint4* Whi = (const uint4*)g_whi;
    const uint4* Wlo = (const uint4*)g_wlo;

    const int w    = t >> 5;
    const int lane = t & 31;
    const int wm   = (w & 3) * 32;
    const int wn   = (w >> 2) * 32;

    float acc[2][4][4];
#pragma unroll
    for (int mi = 0; mi < 2; mi++)
#pragma unroll
        for (int nf = 0; nf < 4; nf++)
#pragma unroll
            for (int r = 0; r < 4; r++) acc[mi][nf][r] = 0.f;

    const int lm = lane >> 3;        // ldmatrix matrix id 0..3
    const int lr = lane & 7;         // row within 8

    const int arow0 = t >> 3, au = t & 7;
    const uint32_t aoff0 = arow0 * 128 + ((((uint32_t)au) ^ (arow0 & 7)) << 4);
    const int brow0 = t >> 3;
    const uint32_t boff0 = brow0 * 128 + ((((uint32_t)au) ^ (brow0 & 7)) << 4);

    auto load_tile = [&](int kc, uint32_t bo) {
        const int ku = kc >> 3;
#pragma unroll
        for (int i = 0; i < 4; i++) {
            int row = arow0 + 32 * i;
            uint32_t off = aoff0 + 32 * i * 128;
            int gidx = (m0 + row) * 32 + ku + au;
            cp16(sbase + bo + AHI + off, Xhi + gidx);
            cp16(sbase + bo + ALO + off, Xlo + gidx);
        }
#pragma unroll
        for (int i = 0; i < 2; i++) {
            int row = brow0 + 32 * i;
            uint32_t off = boff0 + 32 * i * 128;
            int gidx = (c0 + row) * 32 + ku + au;
            cp16(sbase + bo + BHI + off, Whi + gidx);
            cp16(sbase + bo + BLO + off, Wlo + gidx);
        }
        asm volatile("cp.async.commit_group;");
    };

    load_tile(0, 0);

#pragma unroll
    for (int it = 0; it < 4; it++) {
        const uint32_t bo = (uint32_t)(it & 1) * BUFSZ;
        if (it < 3) {
            load_tile((it + 1) * 64, (uint32_t)((it + 1) & 1) * BUFSZ);
            asm volatile("cp.async.wait_group 1;");
        } else {
            asm volatile("cp.async.wait_group 0;");
        }
        __syncthreads();

#pragma unroll
        for (int ks = 0; ks < 4; ks++) {
            uint32_t ah[2][4], al[2][4], bh[2][4], bl[2][4];
#pragma unroll
            for (int mi = 0; mi < 2; mi++) {
                int row  = wm + mi * 16 + lr + (lm & 1) * 8;
                int unit = ks * 2 + (lm >> 1);
                uint32_t off = row * 128 + (((uint32_t)unit ^ (row & 7)) << 4);
                ldsm4(ah[mi], sbase + bo + AHI + off);
                ldsm4(al[mi], sbase + bo + ALO + off);
            }
#pragma unroll
            for (int bi = 0; bi < 2; bi++) {
                int n    = wn + bi * 16 + lr + (lm >> 1) * 8;
                int unit = ks * 2 + (lm & 1);
                uint32_t off = n * 128 + (((uint32_t)unit ^ (n & 7)) << 4);
                ldsm4(bh[bi], sbase + bo + BHI + off);
                ldsm4(bl[bi], sbase + bo + BLO + off);
            }
#pragma unroll
            for (int mi = 0; mi < 2; mi++) {
#pragma unroll
                for (int nf = 0; nf < 4; nf++) {
                    int bi = nf >> 1, hf = (nf & 1) * 2;
                    mma16816(acc[mi][nf], ah[mi][0], ah[mi][1], ah[mi][2], ah[mi][3],
                             bh[bi][hf], bh[bi][hf + 1]);
                    mma16816(acc[mi][nf], ah[mi][0], ah[mi][1], ah[mi][2], ah[mi][3],
                             bl[bi][hf], bl[bi][hf + 1]);
                    mma16816(acc[mi][nf], al[mi][0], al[mi][1], al[mi][2], al[mi][3],
                             bh[bi][hf], bh[bi][hf + 1]);
                }
            }
        }
        __syncthreads();
    }

    // ---- epilogue (+ per-row sqnorm atomics for self cols) ----
    const int rquad = lane >> 2;      // 0..7
    const int cpair = (lane & 3) * 2; // 0,2,4,6
#pragma unroll
    for (int mi = 0; mi < 2; mi++) {
        float sqh[2] = {0.f, 0.f};
#pragma unroll
        for (int nf = 0; nf < 4; nf++) {
            int colg = c0 + wn + nf * 8 + cpair;
#pragma unroll
            for (int half = 0; half < 2; half++) {
                int row = m0 + wm + mi * 16 + rquad + half * 8;
                float2 v = make_float2(acc[mi][nf][half * 2],
                                       acc[mi][nf][half * 2 + 1]);
                if (self) {
                    v.x += __ldg(bx + colg);
                    v.y += __ldg(bx + colg + 1);
                    sqh[half] += v.x * v.x + v.y * v.y;
                    *(float2*)(g_hpre + row * CCH + colg) = v;
                } else {
                    *(float2*)(g_yn + row * FF + (colg - 256)) = v;
                }
            }
        }
        if (self) {
#pragma unroll
            for (int half = 0; half < 2; half++) {
                float s = sqh[half];
                s += __shfl_xor_sync(0xffffffffu, s, 1);
                s += __shfl_xor_sync(0xffffffffu, s, 2);
                if ((lane & 3) == 0)
                    atomicAdd(&g_sqn[m0 + wm + mi * 16 + rquad + half * 8], s);
            }
        }
    }
}

// ---------------------------------------------------------------------------
// K2: gather-mean through shared memory (+ per-row sqnorm atomics).
// (byte-identical to the 49.3us best)
// ---------------------------------------------------------------------------
__global__ __launch_bounds__(256) void k_gather(const int* __restrict__ i1,
                                                const int* __restrict__ i2,
                                                const int* __restrict__ i3,
                                                const float* __restrict__ bn) {
    extern __shared__ float smf[];
    float4* syn  = (float4*)smf;                 // 512 rows * 16 float4
    int*    sidx = (int*)(smf + 512 * 64);       // [3][128][32]

    const int t    = threadIdx.x;
    const int lane = t & 31;
    const int ct = blockIdx.x;   // 0..3 channel chunk (64 ch)
    const int rt = blockIdx.y;   // 0..3 output-row tile (128 rows)
    const int b  = blockIdx.z;   // 0..7

    const float4* yn4 = (const float4*)g_yn;
#pragma unroll
    for (int i = 0; i < 32; i++) {
        int lin = t + 256 * i;                  // = row*16 + c4
        int row = lin >> 4, c4 = lin & 15;
        syn[lin] = yn4[(b * 512 + row) * 64 + ct * 16 + c4];
    }
#pragma unroll
    for (int i = 0; i < 48; i++) {
        int lin = t + 256 * i;                  // 0..12287
        int s   = lin >> 12;
        int rem = lin & 4095;                   // rl*32 + k
        const int* ip = (s == 0) ? i1 : (s == 1) ? i2 : i3;
        sidx[lin] = ip[rt * 4096 + rem];
    }
    __syncthreads();

    const int cq = t & 15;
    const int rg = t >> 4;
    const float4 bias = ((const float4*)bn)[ct * 16 + cq];

    for (int r8 = 0; r8 < 8; r8++) {
        const int rl  = r8 * 16 + rg;
        const int row = b * 512 + rt * 128 + rl;
        float sq = 0.f;
        for (int s = 0; s < 3; s++) {
            const int* ip = sidx + s * 4096 + rl * 32;
            float4 acc = make_float4(0.f, 0.f, 0.f, 0.f);
#pragma unroll
            for (int k = 0; k < 32; k++) {
                int j = ip[k];
                float4 v = syn[j * 16 + cq];
                acc.x += v.x; acc.y += v.y; acc.z += v.z; acc.w += v.w;
            }
            float4 o;
            o.x = acc.x * (1.f / 32.f) + bias.x;
            o.y = acc.y * (1.f / 32.f) + bias.y;
            o.z = acc.z * (1.f / 32.f) + bias.z;
            o.w = acc.w * (1.f / 32.f) + bias.w;
            sq += o.x * o.x + o.y * o.y + o.z * o.z + o.w * o.w;
            ((float4*)g_hpre)[row * 256 + 64 + s * 64 + ct * 16 + cq] = o;
        }
#pragma unroll
        for (int o2 = 8; o2; o2 >>= 1)
            sq += __shfl_xor_sync(0xffffffffu, sq, o2);
        if ((lane & 15) == 0) atomicAdd(&g_sqn[row], sq);
    }
}

// ---------------------------------------------------------------------------
// K3: BN channel sums only (row norms precomputed in g_sqn) — barrier-free.
// grid 512, 8 rows/block, ~50 regs -> 3-4 CTA/SM. Thread t owns channel
// quad t; sums are thread-private; 8 spread-address global atomics.
// ---------------------------------------------------------------------------
__global__ __launch_bounds__(256) void k_stats() {
    __shared__ float rns[8];
    const int t  = threadIdx.x;
    const int r0 = blockIdx.x * 8;
    const float4* hp4 = (const float4*)g_hpre;

    if (t < 8) {
        float s = g_sqn[r0 + t];
        rns[t] = 1.f / fmaxf(sqrtf(s), 1e-12f);
    }

    float4 v[8];
#pragma unroll
    for (int r = 0; r < 8; r++) v[r] = hp4[(r0 + r) * 256 + t];
    __syncthreads();

    float4 cs = make_float4(0.f, 0.f, 0.f, 0.f);
    float4 cq = make_float4(0.f, 0.f, 0.f, 0.f);
#pragma unroll
    for (int r = 0; r < 8; r++) {
        const float rn = rns[r];
        float u0 = fmaxf(v[r].x * rn, 0.f);
        float u1 = fmaxf(v[r].y * rn, 0.f);
        float u2 = fmaxf(v[r].z * rn, 0.f);
        float u3 = fmaxf(v[r].w * rn, 0.f);
        cs.x += u0; cq.x += u0 * u0;
        cs.y += u1; cq.y += u1 * u1;
        cs.z += u2; cq.z += u2 * u2;
        cs.w += u3; cq.w += u3 * u3;
    }
    atomicAdd(&g_sum[4 * t + 0], cs.x);
    atomicAdd(&g_sum[4 * t + 1], cs.y);
    atomicAdd(&g_sum[4 * t + 2], cs.z);
    atomicAdd(&g_sum[4 * t + 3], cs.w);
    atomicAdd(&g_sumsq[4 * t + 0], cq.x);
    atomicAdd(&g_sumsq[4 * t + 1], cq.y);
    atomicAdd(&g_sumsq[4 * t + 2], cq.z);
    atomicAdd(&g_sumsq[4 * t + 3], cq.w);
}

// ---------------------------------------------------------------------------
// K4: finalize (per-thread, redundant per block) + apply.
// grid 512, 8 rows/block, batched prefetch (r10 measured-good structure);
// rn recomputed from g_sqn once per row via smem.
// ---------------------------------------------------------------------------
__global__ __launch_bounds__(256) void k_apply(float* __restrict__ out,
                                               const float* __restrict__ gamma,
                                               const float* __restrict__ beta) {
    __shared__ float rns[8];
    const int t = threadIdx.x;
    const int r0 = blockIdx.x * 8;

    if (t < 8) {
        float s = g_sqn[r0 + t];
        rns[t] = 1.f / fmaxf(sqrtf(s), 1e-12f);
    }

    float4 s  = ((const float4*)g_sum)[t];
    float4 q  = ((const float4*)g_sumsq)[t];
    float4 ga = ((const float4*)gamma)[t];
    float4 be = ((const float4*)beta)[t];
    float4 sc, sh;
    {
        float m, va;
        m = s.x * (1.f/4096.f); va = q.x * (1.f/4096.f) - m*m;
        sc.x = ga.x * rsqrtf(va + 1e-5f); sh.x = be.x - m * sc.x;
        m = s.y * (1.f/4096.f); va = q.y * (1.f/4096.f) - m*m;
        sc.y = ga.y * rsqrtf(va + 1e-5f); sh.y = be.y - m * sc.y;
        m = s.z * (1.f/4096.f); va = q.z * (1.f/4096.f) - m*m;
        sc.z = ga.z * rsqrtf(va + 1e-5f); sh.z = be.z - m * sc.z;
        m = s.w * (1.f/4096.f); va = q.w * (1.f/4096.f) - m*m;
        sc.w = ga.w * rsqrtf(va + 1e-5f); sh.w = be.w - m * sc.w;
    }
    const float4* hp4 = (const float4*)g_hpre;

    float4 v[8];
#pragma unroll
    for (int r = 0; r < 8; r++) v[r] = hp4[(r0 + r) * 256 + t];
    __syncthreads();
#pragma unroll
    for (int r = 0; r < 8; r++) {
        const float rn = rns[r];
        float4 o;
        o.x = fmaxf(v[r].x * rn, 0.f) * sc.x + sh.x;
        o.y = fmaxf(v[r].y * rn, 0.f) * sc.y + sh.y;
        o.z = fmaxf(v[r].z * rn, 0.f) * sc.z + sh.z;
        o.w = fmaxf(v[r].w * rn, 0.f) * sc.w + sh.w;
        ((float4*)out)[(r0 + r) * 256 + t] = o;
    }
}

// ---------------------------------------------------------------------------
extern "C" void kernel_launch(void* const* d_in, const int* in_sizes, int n_in,
                              void* d_out, int out_size) {
    const float* x     = (const float*)d_in[0];
    const int*   i1    = (const int*)  d_in[1];
    const int*   i2    = (const int*)  d_in[2];
    const int*   i3    = (const int*)  d_in[3];
    const float* Wx    = (const float*)d_in[4];
    const float* bx    = (const float*)d_in[5];
    const float* Wn    = (const float*)d_in[6];
    const float* bnb   = (const float*)d_in[7];
    const float* gamma = (const float*)d_in[8];
    const float* beta  = (const float*)d_in[9];
    float* out = (float*)d_out;

    cudaFuncSetAttribute(k_gemm,   cudaFuncAttributeMaxDynamicSharedMemorySize, 98304);
    cudaFuncSetAttribute(k_gather, cudaFuncAttributeMaxDynamicSharedMemorySize, 180224);

    k_split<<<1152, 256>>>(x, Wx, Wn);
    k_gemm<<<dim3(8, 32), 256, 98304>>>(bx);
    k_gather<<<dim3(4, 4, 8), 256, 180224>>>(i1, i2, i3, bnb);
    k_stats<<<512, 256>>>();
    k_apply<<<512, 256>>>(out, gamma, beta);
}

// round 16
// speedup vs baseline: 1.4389x; 1.4389x over previous
#include <cuda_runtime.h>
#include <cuda_bf16.h>
#include <cstdint>

// Problem constants
#define CCH  1024      // 4*FOUT
#define RR   4096      // B*N
#define FF   256

// Scratch (device globals; no allocation allowed)
__device__ float g_hpre[RR * CCH];   // concat [self, h1, h2, h3] pre-norm
__device__ float g_yn[RR * FF];      // x @ Wn^T (no bias)
__device__ float g_sqn[RR];          // per-row sum of squares (atomics)
__device__ float g_sum[CCH];
__device__ float g_sumsq[CCH];
__device__ unsigned int g_tick;      // monotonic grid-barrier ticket

// pre-split bf16 planes (X: [4096][256], W combined [Wx;Wn]: [512][256])
__device__ uint2 g_xhi[RR * FF / 4];
__device__ uint2 g_xlo[RR * FF / 4];
__device__ uint2 g_whi[512 * FF / 4];
__device__ uint2 g_wlo[512 * FF / 4];

// ---------------------------------------------------------------------------
// MMA helpers (bf16 m16n8k16, fp32 accum)
// ---------------------------------------------------------------------------
__device__ __forceinline__ void mma16816(float c[4], uint32_t a0, uint32_t a1,
                                         uint32_t a2, uint32_t a3,
                                         uint32_t b0, uint32_t b1) {
    asm volatile(
        "mma.sync.aligned.m16n8k16.row.col.f32.bf16.bf16.f32 "
        "{%0,%1,%2,%3}, {%4,%5,%6,%7}, {%8,%9}, {%0,%1,%2,%3};"
        : "+f"(c[0]), "+f"(c[1]), "+f"(c[2]), "+f"(c[3])
        : "r"(a0), "r"(a1), "r"(a2), "r"(a3), "r"(b0), "r"(b1));
}

__device__ __forceinline__ void ldsm4(uint32_t r[4], uint32_t addr) {
    asm volatile("ldmatrix.sync.aligned.m8n8.x4.shared.b16 {%0,%1,%2,%3}, [%4];"
                 : "=r"(r[0]), "=r"(r[1]), "=r"(r[2]), "=r"(r[3]) : "r"(addr));
}

__device__ __forceinline__ void cp16(uint32_t saddr, const void* gaddr) {
    asm volatile("cp.async.cg.shared.global [%0], [%1], 16;"
                 :: "r"(saddr), "l"(gaddr));
}

__device__ __forceinline__ uint32_t pack_bf16(float a, float b) {
    __nv_bfloat162 t = __halves2bfloat162(__float2bfloat16_rn(a),
                                          __float2bfloat16_rn(b));
    return *reinterpret_cast<uint32_t*>(&t);
}

// split fp32 float4 -> hi pair-packed (2 regs) and lo pair-packed (2 regs)
__device__ __forceinline__ void split4(float4 v, uint2& hi, uint2& lo) {
    float hx = __bfloat162float(__float2bfloat16_rn(v.x));
    float hy = __bfloat162float(__float2bfloat16_rn(v.y));
    float hz = __bfloat162float(__float2bfloat16_rn(v.z));
    float hw = __bfloat162float(__float2bfloat16_rn(v.w));
    hi.x = pack_bf16(v.x, v.y);
    hi.y = pack_bf16(v.z, v.w);
    lo.x = pack_bf16(v.x - hx, v.y - hy);
    lo.y = pack_bf16(v.z - hz, v.w - hw);
}

// ---------------------------------------------------------------------------
// K0: pre-split X and W=[Wx;Wn] into bf16 hi/lo planes; zero accumulators.
// ---------------------------------------------------------------------------
__global__ __launch_bounds__(256) void k_split(const float* __restrict__ X,
                                               const float* __restrict__ Wx,
                                               const float* __restrict__ Wn) {
    int i = blockIdx.x * 256 + threadIdx.x;
    if (i < 262144) {
        float4 v = ((const float4*)X)[i];
        uint2 hi, lo; split4(v, hi, lo);
        g_xhi[i] = hi; g_xlo[i] = lo;
    } else {
        int j = i - 262144;                 // 0..32767
        float4 v = (j < 16384) ? ((const float4*)Wx)[j]
                               : ((const float4*)Wn)[j - 16384];
        uint2 hi, lo; split4(v, hi, lo);
        g_whi[j] = hi; g_wlo[j] = lo;
        if (j < 4096) g_sqn[j] = 0.f;
        if (j < 256) {                       // fold k_zero
            ((float*)g_sum)[j]     = 0.f; ((float*)g_sum)[j + 256]   = 0.f;
            ((float*)g_sum)[j+512] = 0.f; ((float*)g_sum)[j + 768]   = 0.f;
            ((float*)g_sumsq)[j]     = 0.f; ((float*)g_sumsq)[j + 256] = 0.f;
            ((float*)g_sumsq)[j+512] = 0.f; ((float*)g_sumsq)[j + 768] = 0.f;
        }
    }
}

// ---------------------------------------------------------------------------
// K1: C[4096,512] = X[4096,256] @ W^T via split-bf16 tensor-core MMA.
// CTA tile 128(M) x 64(N), grid (8,32)=256 blocks, cp.async double buffer.
// Self blocks additionally accumulate per-row sum-of-squares into g_sqn.
// (byte-identical to the 49.3us best)
// ---------------------------------------------------------------------------
__global__ __launch_bounds__(256) void k_gemm(const float* __restrict__ bx) {
    extern __shared__ uint8_t sm[];
    const uint32_t AHI = 0, ALO = 16384, BHI = 32768, BLO = 40960;
    const uint32_t BUFSZ = 49152;
    const uint32_t sbase = (uint32_t)__cvta_generic_to_shared(sm);

    const int t  = threadIdx.x;
    const int m0 = blockIdx.y * 128;
    const int c0 = blockIdx.x * 64;          // combined W row base (0..448)
    const bool self = (c0 < 256);

    const uint4* Xhi = (const uint4*)g_xhi;  // row stride 32 uint4
    const uint4* Xlo = (const uint4*)g_xlo;
    const uint4* Whi = (const uint4*)g_whi;
    const uint4* Wlo = (const uint4*)g_wlo;

    const int w    = t >> 5;
    const int lane = t & 31;
    const int wm   = (w & 3) * 32;
    const int wn   = (w >> 2) * 32;

    float acc[2][4][4];
#pragma unroll
    for (int mi = 0; mi < 2; mi++)
#pragma unroll
        for (int nf = 0; nf < 4; nf++)
#pragma unroll
            for (int r = 0; r < 4; r++) acc[mi][nf][r] = 0.f;

    const int lm = lane >> 3;        // ldmatrix matrix id 0..3
    const int lr = lane & 7;         // row within 8

    const int arow0 = t >> 3, au = t & 7;
    const uint32_t aoff0 = arow0 * 128 + ((((uint32_t)au) ^ (arow0 & 7)) << 4);
    const int brow0 = t >> 3;
    const uint32_t boff0 = brow0 * 128 + ((((uint32_t)au) ^ (brow0 & 7)) << 4);

    auto load_tile = [&](int kc, uint32_t bo) {
        const int ku = kc >> 3;
#pragma unroll
        for (int i = 0; i < 4; i++) {
            int row = arow0 + 32 * i;
            uint32_t off = aoff0 + 32 * i * 128;
            int gidx = (m0 + row) * 32 + ku + au;
            cp16(sbase + bo + AHI + off, Xhi + gidx);
            cp16(sbase + bo + ALO + off, Xlo + gidx);
        }
#pragma unroll
        for (int i = 0; i < 2; i++) {
            int row = brow0 + 32 * i;
            uint32_t off = boff0 + 32 * i * 128;
            int gidx = (c0 + row) * 32 + ku + au;
            cp16(sbase + bo + BHI + off, Whi + gidx);
            cp16(sbase + bo + BLO + off, Wlo + gidx);
        }
        asm volatile("cp.async.commit_group;");
    };

    load_tile(0, 0);

#pragma unroll
    for (int it = 0; it < 4; it++) {
        const uint32_t bo = (uint32_t)(it & 1) * BUFSZ;
        if (it < 3) {
            load_tile((it + 1) * 64, (uint32_t)((it + 1) & 1) * BUFSZ);
            asm volatile("cp.async.wait_group 1;");
        } else {
            asm volatile("cp.async.wait_group 0;");
        }
        __syncthreads();

#pragma unroll
        for (int ks = 0; ks < 4; ks++) {
            uint32_t ah[2][4], al[2][4], bh[2][4], bl[2][4];
#pragma unroll
            for (int mi = 0; mi < 2; mi++) {
                int row  = wm + mi * 16 + lr + (lm & 1) * 8;
                int unit = ks * 2 + (lm >> 1);
                uint32_t off = row * 128 + (((uint32_t)unit ^ (row & 7)) << 4);
                ldsm4(ah[mi], sbase + bo + AHI + off);
                ldsm4(al[mi], sbase + bo + ALO + off);
            }
#pragma unroll
            for (int bi = 0; bi < 2; bi++) {
                int n    = wn + bi * 16 + lr + (lm >> 1) * 8;
                int unit = ks * 2 + (lm & 1);
                uint32_t off = n * 128 + (((uint32_t)unit ^ (n & 7)) << 4);
                ldsm4(bh[bi], sbase + bo + BHI + off);
                ldsm4(bl[bi], sbase + bo + BLO + off);
            }
#pragma unroll
            for (int mi = 0; mi < 2; mi++) {
#pragma unroll
                for (int nf = 0; nf < 4; nf++) {
                    int bi = nf >> 1, hf = (nf & 1) * 2;
                    mma16816(acc[mi][nf], ah[mi][0], ah[mi][1], ah[mi][2], ah[mi][3],
                             bh[bi][hf], bh[bi][hf + 1]);
                    mma16816(acc[mi][nf], ah[mi][0], ah[mi][1], ah[mi][2], ah[mi][3],
                             bl[bi][hf], bl[bi][hf + 1]);
                    mma16816(acc[mi][nf], al[mi][0], al[mi][1], al[mi][2], al[mi][3],
                             bh[bi][hf], bh[bi][hf + 1]);
                }
            }
        }
        __syncthreads();
    }

    // ---- epilogue (+ per-row sqnorm atomics for self cols) ----
    const int rquad = lane >> 2;      // 0..7
    const int cpair = (lane & 3) * 2; // 0,2,4,6
#pragma unroll
    for (int mi = 0; mi < 2; mi++) {
        float sqh[2] = {0.f, 0.f};
#pragma unroll
        for (int nf = 0; nf < 4; nf++) {
            int colg = c0 + wn + nf * 8 + cpair;
#pragma unroll
            for (int half = 0; half < 2; half++) {
                int row = m0 + wm + mi * 16 + rquad + half * 8;
                float2 v = make_float2(acc[mi][nf][half * 2],
                                       acc[mi][nf][half * 2 + 1]);
                if (self) {
                    v.x += __ldg(bx + colg);
                    v.y += __ldg(bx + colg + 1);
                    sqh[half] += v.x * v.x + v.y * v.y;
                    *(float2*)(g_hpre + row * CCH + colg) = v;
                } else {
                    *(float2*)(g_yn + row * FF + (colg - 256)) = v;
                }
            }
        }
        if (self) {
#pragma unroll
            for (int half = 0; half < 2; half++) {
                float s = sqh[half];
                s += __shfl_xor_sync(0xffffffffu, s, 1);
                s += __shfl_xor_sync(0xffffffffu, s, 2);
                if ((lane & 3) == 0)
                    atomicAdd(&g_sqn[m0 + wm + mi * 16 + rquad + half * 8], s);
            }
        }
    }
}

// ---------------------------------------------------------------------------
// K2: gather-mean through shared memory (+ per-row sqnorm atomics).
// (byte-identical to the 49.3us best)
// ---------------------------------------------------------------------------
__global__ __launch_bounds__(256) void k_gather(const int* __restrict__ i1,
                                                const int* __restrict__ i2,
                                                const int* __restrict__ i3,
                                                const float* __restrict__ bn) {
    extern __shared__ float smf[];
    float4* syn  = (float4*)smf;                 // 512 rows * 16 float4
    int*    sidx = (int*)(smf + 512 * 64);       // [3][128][32]

    const int t    = threadIdx.x;
    const int lane = t & 31;
    const int ct = blockIdx.x;   // 0..3 channel chunk (64 ch)
    const int rt = blockIdx.y;   // 0..3 output-row tile (128 rows)
    const int b  = blockIdx.z;   // 0..7

    const float4* yn4 = (const float4*)g_yn;
#pragma unroll
    for (int i = 0; i < 32; i++) {
        int lin = t + 256 * i;                  // = row*16 + c4
        int row = lin >> 4, c4 = lin & 15;
        syn[lin] = yn4[(b * 512 + row) * 64 + ct * 16 + c4];
    }
#pragma unroll
    for (int i = 0; i < 48; i++) {
        int lin = t + 256 * i;                  // 0..12287
        int s   = lin >> 12;
        int rem = lin & 4095;                   // rl*32 + k
        const int* ip = (s == 0) ? i1 : (s == 1) ? i2 : i3;
        sidx[lin] = ip[rt * 4096 + rem];
    }
    __syncthreads();

    const int cq = t & 15;
    const int rg = t >> 4;
    const float4 bias = ((const float4*)bn)[ct * 16 + cq];

    for (int r8 = 0; r8 < 8; r8++) {
        const int rl  = r8 * 16 + rg;
        const int row = b * 512 + rt * 128 + rl;
        float sq = 0.f;
        for (int s = 0; s < 3; s++) {
            const int* ip = sidx + s * 4096 + rl * 32;
            float4 acc = make_float4(0.f, 0.f, 0.f, 0.f);
#pragma unroll
            for (int k = 0; k < 32; k++) {
                int j = ip[k];
                float4 v = syn[j * 16 + cq];
                acc.x += v.x; acc.y += v.y; acc.z += v.z; acc.w += v.w;
            }
            float4 o;
            o.x = acc.x * (1.f / 32.f) + bias.x;
            o.y = acc.y * (1.f / 32.f) + bias.y;
            o.z = acc.z * (1.f / 32.f) + bias.z;
            o.w = acc.w * (1.f / 32.f) + bias.w;
            sq += o.x * o.x + o.y * o.y + o.z * o.z + o.w * o.w;
            ((float4*)g_hpre)[row * 256 + 64 + s * 64 + ct * 16 + cq] = o;
        }
#pragma unroll
        for (int o2 = 8; o2; o2 >>= 1)
            sq += __shfl_xor_sync(0xffffffffu, sq, o2);
        if ((lane & 15) == 0) atomicAdd(&g_sqn[row], sq);
    }
}

// ---------------------------------------------------------------------------
// K3: FUSED stats + apply (row norms precomputed in g_sqn).
// grid 128 (all co-resident), block 512: thread t owns channel PAIR t
// (channels 2t, 2t+1) for the block's 32 rows; v[32] float2 in regs
// (~95 regs at 512 thr -> 16 warps/SM, 2x the warps of the r13 version).
//   rn from g_sqn -> thread-private channel sums -> 4 atomics ->
//   grid barrier -> finalize own channels -> apply from registers.
// Atomic regime: 2048 updates/block to 2048 addresses (128 updates/addr).
// ---------------------------------------------------------------------------
__global__ __launch_bounds__(512, 1) void k_statsapply(float* __restrict__ out,
                                                       const float* __restrict__ gamma,
                                                       const float* __restrict__ beta) {
    __shared__ float rns[32];

    const int t  = threadIdx.x;          // 0..511, channel pair t
    const int r0 = blockIdx.x * 32;
    const float2* hp2 = (const float2*)g_hpre;   // row stride 512 float2

    if (t < 32) {
        float s = g_sqn[r0 + t];
        rns[t] = 1.f / fmaxf(sqrtf(s), 1e-12f);
    }

    float2 v[32];
#pragma unroll
    for (int r = 0; r < 32; r++) v[r] = hp2[(r0 + r) * 512 + t];
    __syncthreads();

    float2 cs = make_float2(0.f, 0.f);
    float2 cq = make_float2(0.f, 0.f);
#pragma unroll
    for (int r = 0; r < 32; r++) {
        const float rn = rns[r];
        float u0 = fmaxf(v[r].x * rn, 0.f);
        float u1 = fmaxf(v[r].y * rn, 0.f);
        cs.x += u0; cq.x += u0 * u0;
        cs.y += u1; cq.y += u1 * u1;
    }
    atomicAdd(&g_sum[2 * t + 0], cs.x);
    atomicAdd(&g_sum[2 * t + 1], cs.y);
    atomicAdd(&g_sumsq[2 * t + 0], cq.x);
    atomicAdd(&g_sumsq[2 * t + 1], cq.y);

    // ---- software grid barrier (monotonic epoch ticket) ----
    __threadfence();
    __syncthreads();
    if (t == 0) {
        unsigned int ticket = atomicAdd(&g_tick, 1u);
        unsigned int target = (ticket / gridDim.x + 1u) * gridDim.x;
        while (true) {
            unsigned int x;
            asm volatile("ld.global.acquire.gpu.u32 %0, [%1];"
                         : "=r"(x) : "l"(&g_tick));
            if (x >= target) break;
            __nanosleep(64);
        }
    }
    __syncthreads();

    // ---- finalize (own 2 channels) + apply from registers ----
    float2 s2, q2;
    asm volatile("ld.global.cg.v2.f32 {%0,%1}, [%2];"
                 : "=f"(s2.x), "=f"(s2.y) : "l"(g_sum + 2 * t));
    asm volatile("ld.global.cg.v2.f32 {%0,%1}, [%2];"
                 : "=f"(q2.x), "=f"(q2.y) : "l"(g_sumsq + 2 * t));
    float2 ga = ((const float2*)gamma)[t];
    float2 be = ((const float2*)beta)[t];
    float2 sc, sh;
    {
        float m, va;
        m = s2.x * (1.f/4096.f); va = q2.x * (1.f/4096.f) - m*m;
        sc.x = ga.x * rsqrtf(va + 1e-5f); sh.x = be.x - m * sc.x;
        m = s2.y * (1.f/4096.f); va = q2.y * (1.f/4096.f) - m*m;
        sc.y = ga.y * rsqrtf(va + 1e-5f); sh.y = be.y - m * sc.y;
    }
#pragma unroll
    for (int r = 0; r < 32; r++) {
        const float rn = rns[r];
        float2 o;
        o.x = fmaxf(v[r].x * rn, 0.f) * sc.x + sh.x;
        o.y = fmaxf(v[r].y * rn, 0.f) * sc.y + sh.y;
        ((float2*)out)[(r0 + r) * 512 + t] = o;
    }
}

// ---------------------------------------------------------------------------
extern "C" void kernel_launch(void* const* d_in, const int* in_sizes, int n_in,
                              void* d_out, int out_size) {
    const float* x     = (const float*)d_in[0];
    const int*   i1    = (const int*)  d_in[1];
    const int*   i2    = (const int*)  d_in[2];
    const int*   i3    = (const int*)  d_in[3];
    const float* Wx    = (const float*)d_in[4];
    const float* bx    = (const float*)d_in[5];
    const float* Wn    = (const float*)d_in[6];
    const float* bnb   = (const float*)d_in[7];
    const float* gamma = (const float*)d_in[8];
    const float* beta  = (const float*)d_in[9];
    float* out = (float*)d_out;

    cudaFuncSetAttribute(k_gemm,   cudaFuncAttributeMaxDynamicSharedMemorySize, 98304);
    cudaFuncSetAttribute(k_gather, cudaFuncAttributeMaxDynamicSharedMemorySize, 180224);

    k_split<<<1152, 256>>>(x, Wx, Wn);
    k_gemm<<<dim3(8, 32), 256, 98304>>>(bx);
    k_gather<<<dim3(4, 4, 8), 256, 180224>>>(i1, i2, i3, bnb);
    k_statsapply<<<128, 512>>>(out, gamma, beta);
}